// round 7
// baseline (speedup 1.0000x reference)
#include <cuda_runtime.h>
#include <stdint.h>

// ============================================================================
// ImpulseNoise — bit-exact JAX (threefry_partitionable) salt & pepper.
// key=(0,42); k_flip = tf20(key,(0,0)); k_salt = tf20(key,(0,1))
// bits(i) = fold(tf20(k, (0, i)));  u = (bits>>9)*2^-23
// u <= 0.09f  <=>  bits <= (754974<<9)|511     (rel_err=0 verified R2-R6)
// u <= 0.5    <=>  bits <= 0x800001FF
//
// R7 = R6 hybrid (10/20 rotates as IMAD.WIDE on fma pipe, rest SHF on alu)
//      + __launch_bounds__(256, 8) forcing regs<=32.
// R6 showed the hybrid cuts absolute alu work 14% but regs=40 dropped occ
// to 68% and gave the win back. Same instruction count, restore occupancy.
// Salt hashes remain warp-ballot-compacted (~0.09 hashes/elem).
// ============================================================================

struct U2c { unsigned a, b; };

constexpr U2c threefry20_host(unsigned k0, unsigned k1, unsigned x0, unsigned x1) {
    unsigned ks2 = k0 ^ k1 ^ 0x1BD11BDAu;
    x0 += k0; x1 += k1;
#define TFR_H(r) { x0 += x1; x1 = (x1 << (r)) | (x1 >> (32 - (r))); x1 ^= x0; }
    TFR_H(13) TFR_H(15) TFR_H(26) TFR_H(6)
    x0 += k1;  x1 += ks2 + 1u;
    TFR_H(17) TFR_H(29) TFR_H(16) TFR_H(24)
    x0 += ks2; x1 += k0 + 2u;
    TFR_H(13) TFR_H(15) TFR_H(26) TFR_H(6)
    x0 += k0;  x1 += k1 + 3u;
    TFR_H(17) TFR_H(29) TFR_H(16) TFR_H(24)
    x0 += k1;  x1 += ks2 + 4u;
    TFR_H(13) TFR_H(15) TFR_H(26) TFR_H(6)
    x0 += ks2; x1 += k0 + 5u;
#undef TFR_H
    return U2c{x0, x1};
}

constexpr U2c KFLIP = threefry20_host(0u, 42u, 0u, 0u);
constexpr U2c KSALT = threefry20_host(0u, 42u, 0u, 1u);

constexpr unsigned N_TOTAL = 64u * 3u * 512u * 512u;   // 50331648
constexpr unsigned FLIP_T  = (754974u << 9) | 511u;    // u <= 0.09f
constexpr unsigned SALT_T  = 0x800001FFu;              // u <= 0.5f

// Runtime rotation multipliers (2^r) for the mul-rotated rounds; opaque to ptxas.
struct Mults { unsigned m15, m6, m29, m24; };

// SHF round: x0 += x1; x1 = rotl(x1,r) ^ x0           (alu: SHF + LOP3)
#define TFR_S(r) { x0 += x1; x1 = __funnelshift_l(x1, x1, (r)); x1 ^= x0; }
// MUL round: rotl via IMAD.WIDE (fma), combine (lo|hi)^x0 one LOP3 (alu)
#define TFR_M(mr) { x0 += x1;                                                 \
    unsigned long long p = (unsigned long long)x1 * (unsigned long long)(mr);  \
    x1 = ((unsigned)p | (unsigned)(p >> 32)) ^ x0; }

// Threefry-2x32-20, counter (0, i), returns x0^x1.
template <unsigned K0, unsigned K1>
__device__ __forceinline__ unsigned tf20_fold(unsigned i, const Mults& M) {
    constexpr unsigned KS2 = K0 ^ K1 ^ 0x1BD11BDAu;
    unsigned x1 = i + K1;
    unsigned x0 = x1 + K0;   // round-1 add with x0_init = K0 folded
    x1 = __funnelshift_l(x1, x1, 13); x1 ^= x0;        // finish round 1 (SHF)
    TFR_M(M.m15) TFR_S(26) TFR_M(M.m6)
    x0 += K1;  x1 += KS2 + 1u;
    TFR_S(17) TFR_M(M.m29) TFR_S(16) TFR_M(M.m24)
    x0 += KS2; x1 += K0 + 2u;
    TFR_S(13) TFR_M(M.m15) TFR_S(26) TFR_M(M.m6)
    x0 += K0;  x1 += K1 + 3u;
    TFR_S(17) TFR_M(M.m29) TFR_S(16) TFR_M(M.m24)
    x0 += K1;  x1 += KS2 + 4u;
    TFR_S(13) TFR_M(M.m15) TFR_S(26) TFR_M(M.m6)
    x0 += KS2; x1 += K0 + 5u;
    return x0 ^ x1;
}
#undef TFR_S
#undef TFR_M

// 8 elements per thread; warp covers 256 consecutive elements.
// launch_bounds(256, 8): force regs<=32 so occupancy returns to ~90%+.
__global__ void __launch_bounds__(256, 8)
impulse_noise_kernel(const float* __restrict__ img, float* __restrict__ out,
                     unsigned one) {
    Mults M;
    M.m15 = one << 15; M.m6 = one << 6; M.m29 = one << 29; M.m24 = one << 24;

    unsigned gwarp = (blockIdx.x * 256u + threadIdx.x) >> 5;
    unsigned lane  = threadIdx.x & 31u;
    unsigned base  = gwarp * 256u;
    unsigned i0 = base + 4u * lane;
    unsigned i1 = base + 128u + 4u * lane;

    float4 v0 = *reinterpret_cast<const float4*>(img + i0);
    float4 v1 = *reinterpret_cast<const float4*>(img + i1);

    // Mandatory flip hashes (8 independent chains for ILP).
    bool fl[8];
#pragma unroll
    for (int s = 0; s < 4; ++s)
        fl[s] = tf20_fold<KFLIP.a, KFLIP.b>(i0 + (unsigned)s, M) <= FLIP_T;
#pragma unroll
    for (int s = 0; s < 4; ++s)
        fl[4 + s] = tf20_fold<KFLIP.a, KFLIP.b>(i1 + (unsigned)s, M) <= FLIP_T;

    // Owners store raw values; flipped slots overwritten after the fence.
    *reinterpret_cast<float4*>(out + i0) = v0;
    *reinterpret_cast<float4*>(out + i1) = v1;

    // Warp-uniform flip masks + prefix counts.
    unsigned m[8], cum[9];
    cum[0] = 0;
#pragma unroll
    for (int s = 0; s < 8; ++s) {
        m[s] = __ballot_sync(0xFFFFFFFFu, fl[s]);
        cum[s + 1] = cum[s] + (unsigned)__popc(m[s]);
    }
    unsigned nf = cum[8];

    __syncwarp();  // owner stores happen-before compacted overwrites

    // Compacted salt passes: 32 flips served per pass (~1 pass typical).
    for (unsigned start = 0; start < nf; start += 32u) {
        unsigned r = start + lane;
        if (r < nf) {
            unsigned mm = m[0], rbase = 0u, eoff = 0u;
#pragma unroll
            for (int w = 1; w < 8; ++w) {
                if (r >= cum[w]) {
                    mm = m[w];
                    rbase = cum[w];
                    eoff = (w < 4) ? (unsigned)w : (unsigned)w + 124u;
                }
            }
            unsigned rr = r - rbase;
            unsigned pos = 0u, c;
            c = (unsigned)__popc(mm & 0xFFFFu); if (rr >= c) { rr -= c; pos += 16u; mm >>= 16; }
            c = (unsigned)__popc(mm & 0xFFu);   if (rr >= c) { rr -= c; pos += 8u;  mm >>= 8; }
            c = (unsigned)__popc(mm & 0xFu);    if (rr >= c) { rr -= c; pos += 4u;  mm >>= 4; }
            c = (unsigned)__popc(mm & 0x3u);    if (rr >= c) { rr -= c; pos += 2u;  mm >>= 2; }
            c = mm & 1u;                        if (rr >= c) { pos += 1u; }

            unsigned gi = base + 4u * pos + eoff;
            unsigned bs = tf20_fold<KSALT.a, KSALT.b>(gi, M);
            out[gi] = (bs <= SALT_T) ? 1.0f : 0.0f;
        }
    }
}

extern "C" void kernel_launch(void* const* d_in, const int* in_sizes, int n_in,
                              void* d_out, int out_size) {
    const float* img = (const float*)d_in[0];
    float* out = (float*)d_out;
    constexpr unsigned threads = N_TOTAL / 8u;    // 6291456
    constexpr unsigned blocks  = threads / 256u;  // 24576
    impulse_noise_kernel<<<blocks, 256>>>(img, out, 1u);
}

// round 8
// speedup vs baseline: 1.0365x; 1.0365x over previous
#include <cuda_runtime.h>
#include <stdint.h>

// ============================================================================
// ImpulseNoise — bit-exact JAX (threefry_partitionable) salt & pepper.
// key=(0,42); k_flip = tf20(key,(0,0)); k_salt = tf20(key,(0,1))
// bits(i) = fold(tf20(k, (0, i)));  u = (bits>>9)*2^-23
// u <= 0.09f  <=>  bits <= (754974<<9)|511     (rel_err=0 verified R2-R7)
// u <= 0.5    <=>  bits <= 0x800001FF
//
// R8 = R4 (all-SHF rotates; best measured mix, 159.3us, alu-bound 89.6%)
//      + explicit 3-input-add folding at the 5 key-injection boundaries:
//        x1 += C1;  x0 = x0 + x1 + C0;   // one IADD3 absorbs x0's injection
//      (31 -> 28 add instructions per hash; R5-R7 proved pipe rebalancing
//       via IMAD.WIDE regresses, so we shrink the stream instead).
// Salt hashes remain warp-ballot-compacted (~0.09 hashes/elem).
// ============================================================================

struct U2c { unsigned a, b; };

constexpr U2c threefry20_host(unsigned k0, unsigned k1, unsigned x0, unsigned x1) {
    unsigned ks2 = k0 ^ k1 ^ 0x1BD11BDAu;
    x0 += k0; x1 += k1;
#define TFR_H(r) { x0 += x1; x1 = (x1 << (r)) | (x1 >> (32 - (r))); x1 ^= x0; }
    TFR_H(13) TFR_H(15) TFR_H(26) TFR_H(6)
    x0 += k1;  x1 += ks2 + 1u;
    TFR_H(17) TFR_H(29) TFR_H(16) TFR_H(24)
    x0 += ks2; x1 += k0 + 2u;
    TFR_H(13) TFR_H(15) TFR_H(26) TFR_H(6)
    x0 += k0;  x1 += k1 + 3u;
    TFR_H(17) TFR_H(29) TFR_H(16) TFR_H(24)
    x0 += k1;  x1 += ks2 + 4u;
    TFR_H(13) TFR_H(15) TFR_H(26) TFR_H(6)
    x0 += ks2; x1 += k0 + 5u;
#undef TFR_H
    return U2c{x0, x1};
}

constexpr U2c KFLIP = threefry20_host(0u, 42u, 0u, 0u);
constexpr U2c KSALT = threefry20_host(0u, 42u, 0u, 1u);

constexpr unsigned N_TOTAL = 64u * 3u * 512u * 512u;   // 50331648
constexpr unsigned FLIP_T  = (754974u << 9) | 511u;    // u <= 0.09f
constexpr unsigned SALT_T  = 0x800001FFu;              // u <= 0.5f

// Round-add as mad.lo with opaque one (R3/R4-measured best form).
__device__ __forceinline__ unsigned madr(unsigned a, unsigned one, unsigned b) {
    unsigned d;
    asm("mad.lo.u32 %0, %1, %2, %3;" : "=r"(d) : "r"(a), "r"(one), "r"(b));
    return d;
}

// Plain round: x0 += x1; x1 = rotl(x1,r) ^ x0
#define TFR(r) { x0 = madr(x0, one, x1); x1 = __funnelshift_l(x1, x1, (r)); x1 ^= x0; }
// Injection round: x1 += C1 first, then x0's round-add absorbs its injection
// constant as a single 3-input IADD3:  x0 = x0 + x1 + C0.
#define TFR_INJ(C1, C0, r) {                       \
    x1 += (C1);                                     \
    x0 = x0 + x1 + (C0);                            \
    x1 = __funnelshift_l(x1, x1, (r)); x1 ^= x0; }

// Threefry-2x32-20, counter (0, i), returns x0^x1.
template <unsigned K0, unsigned K1>
__device__ __forceinline__ unsigned tf20_fold(unsigned i, unsigned one) {
    constexpr unsigned KS2 = K0 ^ K1 ^ 0x1BD11BDAu;
    unsigned x1 = i + K1;
    unsigned x0 = x1 + K0;                          // round-1 add, x0_init=K0 folded
    x1 = __funnelshift_l(x1, x1, 13); x1 ^= x0;     // finish round 1
    TFR(15) TFR(26) TFR(6)
    TFR_INJ(KS2 + 1u, K1, 17)                       // round 5 + injection 1
    TFR(29) TFR(16) TFR(24)
    TFR_INJ(K0 + 2u, KS2, 13)                       // round 9 + injection 2
    TFR(15) TFR(26) TFR(6)
    TFR_INJ(K1 + 3u, K0, 17)                        // round 13 + injection 3
    TFR(29) TFR(16) TFR(24)
    TFR_INJ(KS2 + 4u, K1, 13)                       // round 17 + injection 4
    TFR(15) TFR(26) TFR(6)
    // final injection folded into the output fold:
    return (x0 + KS2) ^ (x1 + (K0 + 5u));
}
#undef TFR
#undef TFR_INJ

// 8 elements per thread; warp covers 256 consecutive elements.
__global__ void __launch_bounds__(256)
impulse_noise_kernel(const float* __restrict__ img, float* __restrict__ out,
                     unsigned one) {
    unsigned gwarp = (blockIdx.x * 256u + threadIdx.x) >> 5;
    unsigned lane  = threadIdx.x & 31u;
    unsigned base  = gwarp * 256u;
    unsigned i0 = base + 4u * lane;
    unsigned i1 = base + 128u + 4u * lane;

    float4 v0 = *reinterpret_cast<const float4*>(img + i0);
    float4 v1 = *reinterpret_cast<const float4*>(img + i1);

    // Mandatory flip hashes (8 independent chains for ILP).
    bool fl[8];
#pragma unroll
    for (int s = 0; s < 4; ++s)
        fl[s] = tf20_fold<KFLIP.a, KFLIP.b>(i0 + (unsigned)s, one) <= FLIP_T;
#pragma unroll
    for (int s = 0; s < 4; ++s)
        fl[4 + s] = tf20_fold<KFLIP.a, KFLIP.b>(i1 + (unsigned)s, one) <= FLIP_T;

    // Owners store raw values; flipped slots overwritten after the fence.
    *reinterpret_cast<float4*>(out + i0) = v0;
    *reinterpret_cast<float4*>(out + i1) = v1;

    // Warp-uniform flip masks + prefix counts.
    unsigned m[8], cum[9];
    cum[0] = 0;
#pragma unroll
    for (int s = 0; s < 8; ++s) {
        m[s] = __ballot_sync(0xFFFFFFFFu, fl[s]);
        cum[s + 1] = cum[s] + (unsigned)__popc(m[s]);
    }
    unsigned nf = cum[8];

    __syncwarp();  // owner stores happen-before compacted overwrites

    // Compacted salt passes: 32 flips served per pass (~1 pass typical).
    for (unsigned start = 0; start < nf; start += 32u) {
        unsigned r = start + lane;
        if (r < nf) {
            unsigned mm = m[0], rbase = 0u, eoff = 0u;
#pragma unroll
            for (int w = 1; w < 8; ++w) {
                if (r >= cum[w]) {
                    mm = m[w];
                    rbase = cum[w];
                    eoff = (w < 4) ? (unsigned)w : (unsigned)w + 124u;
                }
            }
            unsigned rr = r - rbase;
            unsigned pos = 0u, c;
            c = (unsigned)__popc(mm & 0xFFFFu); if (rr >= c) { rr -= c; pos += 16u; mm >>= 16; }
            c = (unsigned)__popc(mm & 0xFFu);   if (rr >= c) { rr -= c; pos += 8u;  mm >>= 8; }
            c = (unsigned)__popc(mm & 0xFu);    if (rr >= c) { rr -= c; pos += 4u;  mm >>= 4; }
            c = (unsigned)__popc(mm & 0x3u);    if (rr >= c) { rr -= c; pos += 2u;  mm >>= 2; }
            c = mm & 1u;                        if (rr >= c) { pos += 1u; }

            unsigned gi = base + 4u * pos + eoff;
            unsigned bs = tf20_fold<KSALT.a, KSALT.b>(gi, one);
            out[gi] = (bs <= SALT_T) ? 1.0f : 0.0f;
        }
    }
}

extern "C" void kernel_launch(void* const* d_in, const int* in_sizes, int n_in,
                              void* d_out, int out_size) {
    const float* img = (const float*)d_in[0];
    float* out = (float*)d_out;
    constexpr unsigned threads = N_TOTAL / 8u;    // 6291456
    constexpr unsigned blocks  = threads / 256u;  // 24576
    impulse_noise_kernel<<<blocks, 256>>>(img, out, 1u);
}

// round 9
// speedup vs baseline: 1.0485x; 1.0116x over previous
#include <cuda_runtime.h>
#include <stdint.h>

// ============================================================================
// ImpulseNoise — bit-exact JAX (threefry_partitionable) salt & pepper.
// key=(0,42); k_flip = tf20(key,(0,0)); k_salt = tf20(key,(0,1))
// bits(i) = fold(tf20(k, (0, i)));  u = (bits>>9)*2^-23
// u <= 0.09f  <=>  bits <= (754974<<9)|511     (rel_err=0 verified R2-R8)
// u <= 0.5    <=>  bits <= 0x800001FF
//
// R9 = R4 (all adds as mad.lo->IMAD on fma; best at 159.3us, alu-bound with
//      41 forced alu ops/hash) + exactly FOUR rotates converted to the
//      IMAD.WIDE path (rounds 2,6,10,14; rotations 15,29,15,29).
// Calibrated model (fits R4..R8): alu cyc/elem = 100.6-2.18k,
// fma cyc/elem = 71.6+4.36k (wide = 4 fma slots) -> balance at k=4.
// R7's k=10 overshot into fma-bound; k=4 is the computed optimum.
// Salt hashes remain warp-ballot-compacted (~0.09 hashes/elem).
// ============================================================================

struct U2c { unsigned a, b; };

constexpr U2c threefry20_host(unsigned k0, unsigned k1, unsigned x0, unsigned x1) {
    unsigned ks2 = k0 ^ k1 ^ 0x1BD11BDAu;
    x0 += k0; x1 += k1;
#define TFR_H(r) { x0 += x1; x1 = (x1 << (r)) | (x1 >> (32 - (r))); x1 ^= x0; }
    TFR_H(13) TFR_H(15) TFR_H(26) TFR_H(6)
    x0 += k1;  x1 += ks2 + 1u;
    TFR_H(17) TFR_H(29) TFR_H(16) TFR_H(24)
    x0 += ks2; x1 += k0 + 2u;
    TFR_H(13) TFR_H(15) TFR_H(26) TFR_H(6)
    x0 += k0;  x1 += k1 + 3u;
    TFR_H(17) TFR_H(29) TFR_H(16) TFR_H(24)
    x0 += k1;  x1 += ks2 + 4u;
    TFR_H(13) TFR_H(15) TFR_H(26) TFR_H(6)
    x0 += ks2; x1 += k0 + 5u;
#undef TFR_H
    return U2c{x0, x1};
}

constexpr U2c KFLIP = threefry20_host(0u, 42u, 0u, 0u);
constexpr U2c KSALT = threefry20_host(0u, 42u, 0u, 1u);

constexpr unsigned N_TOTAL = 64u * 3u * 512u * 512u;   // 50331648
constexpr unsigned FLIP_T  = (754974u << 9) | 511u;    // u <= 0.09f
constexpr unsigned SALT_T  = 0x800001FFu;              // u <= 0.5f

// Adds forced to IMAD (fma pipe): d = a*one + b  (R4-measured: all 31 stick).
__device__ __forceinline__ unsigned madr(unsigned a, unsigned one, unsigned b) {
    unsigned d;
    asm("mad.lo.u32 %0, %1, %2, %3;" : "=r"(d) : "r"(a), "r"(one), "r"(b));
    return d;
}
template <unsigned IMM>
__device__ __forceinline__ unsigned madi(unsigned a, unsigned one) {
    unsigned d;
    asm("mad.lo.u32 %0, %1, %2, %3;" : "=r"(d) : "r"(a), "r"(one), "n"(IMM));
    return d;
}

// SHF round (alu: SHF + LOP3; add on fma)
#define TFR(r) { x0 = madr(x0, one, x1); x1 = __funnelshift_l(x1, x1, (r)); x1 ^= x0; }
// WIDE round: rotate via IMAD.WIDE (fma, ~4 slots), combine (lo|hi)^x0 = 1 LOP3
#define TFR_W(mr) { x0 = madr(x0, one, x1);                                    \
    unsigned long long p = (unsigned long long)x1 * (unsigned long long)(mr);   \
    x1 = ((unsigned)p | (unsigned)(p >> 32)) ^ x0; }

// Threefry-2x32-20, counter (0, i), returns x0^x1.
// Rounds 2,6,10,14 (rot 15,29,15,29) use the wide path; rest SHF.
template <unsigned K0, unsigned K1>
__device__ __forceinline__ unsigned tf20_fold(unsigned i, unsigned one,
                                              unsigned m15, unsigned m29) {
    constexpr unsigned KS2 = K0 ^ K1 ^ 0x1BD11BDAu;
    unsigned x1 = madi<K1>(i, one);
    unsigned x0 = madi<K0>(x1, one);                 // round-1 add
    x1 = __funnelshift_l(x1, x1, 13); x1 ^= x0;      // finish round 1
    TFR_W(m15) TFR(26) TFR(6)                        // rounds 2-4
    x0 = madi<K1>(x0, one);   x1 = madi<KS2 + 1u>(x1, one);
    TFR(17) TFR_W(m29) TFR(16) TFR(24)               // rounds 5-8
    x0 = madi<KS2>(x0, one);  x1 = madi<K0 + 2u>(x1, one);
    TFR(13) TFR_W(m15) TFR(26) TFR(6)                // rounds 9-12
    x0 = madi<K0>(x0, one);   x1 = madi<K1 + 3u>(x1, one);
    TFR(17) TFR_W(m29) TFR(16) TFR(24)               // rounds 13-16
    x0 = madi<K1>(x0, one);   x1 = madi<KS2 + 4u>(x1, one);
    TFR(13) TFR(15) TFR(26) TFR(6)                   // rounds 17-20
    x0 = madi<KS2>(x0, one);  x1 = madi<K0 + 5u>(x1, one);
    return x0 ^ x1;
}
#undef TFR
#undef TFR_W

// 8 elements per thread; warp covers 256 consecutive elements.
__global__ void __launch_bounds__(256)
impulse_noise_kernel(const float* __restrict__ img, float* __restrict__ out,
                     unsigned one) {
    unsigned m15 = one << 15, m29 = one << 29;   // opaque 2^r multipliers

    unsigned gwarp = (blockIdx.x * 256u + threadIdx.x) >> 5;
    unsigned lane  = threadIdx.x & 31u;
    unsigned base  = gwarp * 256u;
    unsigned i0 = base + 4u * lane;
    unsigned i1 = base + 128u + 4u * lane;

    float4 v0 = *reinterpret_cast<const float4*>(img + i0);
    float4 v1 = *reinterpret_cast<const float4*>(img + i1);

    // Mandatory flip hashes (8 independent chains for ILP).
    bool fl[8];
#pragma unroll
    for (int s = 0; s < 4; ++s)
        fl[s] = tf20_fold<KFLIP.a, KFLIP.b>(i0 + (unsigned)s, one, m15, m29) <= FLIP_T;
#pragma unroll
    for (int s = 0; s < 4; ++s)
        fl[4 + s] = tf20_fold<KFLIP.a, KFLIP.b>(i1 + (unsigned)s, one, m15, m29) <= FLIP_T;

    // Owners store raw values; flipped slots overwritten after the fence.
    *reinterpret_cast<float4*>(out + i0) = v0;
    *reinterpret_cast<float4*>(out + i1) = v1;

    // Warp-uniform flip masks + prefix counts.
    unsigned m[8], cum[9];
    cum[0] = 0;
#pragma unroll
    for (int s = 0; s < 8; ++s) {
        m[s] = __ballot_sync(0xFFFFFFFFu, fl[s]);
        cum[s + 1] = cum[s] + (unsigned)__popc(m[s]);
    }
    unsigned nf = cum[8];

    __syncwarp();  // owner stores happen-before compacted overwrites

    // Compacted salt passes: 32 flips served per pass (~1 pass typical).
    for (unsigned start = 0; start < nf; start += 32u) {
        unsigned r = start + lane;
        if (r < nf) {
            unsigned mm = m[0], rbase = 0u, eoff = 0u;
#pragma unroll
            for (int w = 1; w < 8; ++w) {
                if (r >= cum[w]) {
                    mm = m[w];
                    rbase = cum[w];
                    eoff = (w < 4) ? (unsigned)w : (unsigned)w + 124u;
                }
            }
            unsigned rr = r - rbase;
            unsigned pos = 0u, c;
            c = (unsigned)__popc(mm & 0xFFFFu); if (rr >= c) { rr -= c; pos += 16u; mm >>= 16; }
            c = (unsigned)__popc(mm & 0xFFu);   if (rr >= c) { rr -= c; pos += 8u;  mm >>= 8; }
            c = (unsigned)__popc(mm & 0xFu);    if (rr >= c) { rr -= c; pos += 4u;  mm >>= 4; }
            c = (unsigned)__popc(mm & 0x3u);    if (rr >= c) { rr -= c; pos += 2u;  mm >>= 2; }
            c = mm & 1u;                        if (rr >= c) { pos += 1u; }

            unsigned gi = base + 4u * pos + eoff;
            unsigned bs = tf20_fold<KSALT.a, KSALT.b>(gi, one, m15, m29);
            out[gi] = (bs <= SALT_T) ? 1.0f : 0.0f;
        }
    }
}

extern "C" void kernel_launch(void* const* d_in, const int* in_sizes, int n_in,
                              void* d_out, int out_size) {
    const float* img = (const float*)d_in[0];
    float* out = (float*)d_out;
    constexpr unsigned threads = N_TOTAL / 8u;    // 6291456
    constexpr unsigned blocks  = threads / 256u;  // 24576
    impulse_noise_kernel<<<blocks, 256>>>(img, out, 1u);
}